// round 3
// baseline (speedup 1.0000x reference)
#include <cuda_runtime.h>
#include <math.h>

#define TOTAL_PTS   172032
#define NBLK        672          // blocks; 64 threads x 4 pts = 256 pts/block
#define BLKS_PER_IMG 84          // 21504 / 256
#define INF_A       1.0e8f
#define NCLS        20
#define LN2_075     0.5198603854199589f   // 0.75 * ln(2)

__device__ float4   g_part[NBLK];
__device__ unsigned g_count = 0;

__device__ __forceinline__ float4 warp_red(float4 a) {
    #pragma unroll
    for (int off = 16; off > 0; off >>= 1) {
        a.x += __shfl_down_sync(0xffffffffu, a.x, off);
        a.y += __shfl_down_sync(0xffffffffu, a.y, off);
        a.z += __shfl_down_sync(0xffffffffu, a.z, off);
        a.w += __shfl_down_sync(0xffffffffu, a.w, off);
    }
    return a;
}

// level-specialized argmin over 32 boxes for 4 points sharing y
template<int LV>
__device__ __forceinline__ void assign_boxes(
    const float4* __restrict__ sbox, const float* __restrict__ sarea,
    float x0, float s, float y, float* best, int* bi)
{
    #pragma unroll 8
    for (int m = 0; m < 32; m++) {
        const float4 bb = sbox[m];
        const float  a  = sarea[m];
        const float tt   = y - bb.y;
        const float bo   = bb.w - y;
        const float mntb = fminf(tt, bo);
        const float mxtb = fmaxf(tt, bo);
        #pragma unroll
        for (int i = 0; i < 4; i++) {
            const float xi = x0 + (float)i * s;
            const float l  = xi - bb.x;
            const float r  = bb.z - xi;
            const float mn = fminf(mntb, fminf(l, r));
            const float mx = fmaxf(mxtb, fmaxf(l, r));
            bool ok;
            if (LV == 0)      ok = (mn > 0.0f) & (mx <= 64.0f);
            else if (LV == 1) ok = (mn > 0.0f) & (mx >= 64.0f) & (mx <= 128.0f);
            else              ok = (mn > 0.0f) & (mx >= 128.0f);
            if (ok & (a < best[i])) { best[i] = a; bi[i] = m; }
        }
    }
}

__global__ __launch_bounds__(64) void k_fused(
    const float* __restrict__ cls0, const float* __restrict__ cls1, const float* __restrict__ cls2,
    const float* __restrict__ reg0, const float* __restrict__ reg1, const float* __restrict__ reg2,
    const float* __restrict__ ctr0, const float* __restrict__ ctr1, const float* __restrict__ ctr2,
    const float* __restrict__ boxes, const int* __restrict__ labels,
    float* __restrict__ out)
{
    __shared__ float4 sbox[32];
    __shared__ float  sarea[32];
    __shared__ int    slab[32];
    __shared__ float4 sw[2];
    __shared__ bool   s_last;

    const int tid = threadIdx.x;
    const int bid = blockIdx.x;

    // ---- target-side (batch-major) block-uniform decode ----
    const int b_img = bid / BLKS_PER_IMG;
    const int pblk  = (bid - b_img * BLKS_PER_IMG) << 8;   // point offset in image

    if (tid < 32) {
        float4 bb = reinterpret_cast<const float4*>(boxes)[b_img * 32 + tid];
        sbox[tid]  = bb;
        sarea[tid] = (bb.z - bb.x) * (bb.w - bb.y);
        slab[tid]  = labels[b_img * 32 + tid];
    }
    __syncthreads();

    const int p0 = pblk + (tid << 2);   // first of 4 points (same row/level)
    int lv, pi, Wsh; float s;
    if (pblk < 16384)      { lv = 0; pi = p0;         Wsh = 7; s = 4.0f;  }
    else if (pblk < 20480) { lv = 1; pi = p0 - 16384; Wsh = 6; s = 8.0f;  }
    else                   { lv = 2; pi = p0 - 20480; Wsh = 5; s = 16.0f; }
    const int   hh = pi >> Wsh;
    const int   ww = pi & ((1 << Wsh) - 1);
    const float x0 = ww * s + 0.5f * s;
    const float y  = hh * s + 0.5f * s;

    // ---- box assignment: 4 independent argmin chains ----
    float best[4] = {INF_A, INF_A, INF_A, INF_A};
    int   bi[4]   = {0, 0, 0, 0};
    if (lv == 0)      assign_boxes<0>(sbox, sarea, x0, s, y, best, bi);
    else if (lv == 1) assign_boxes<1>(sbox, sarea, x0, s, y, best, bi);
    else              assign_boxes<2>(sbox, sarea, x0, s, y, best, bi);

    bool pos[4]; int lab[4];
    #pragma unroll
    for (int i = 0; i < 4; i++) {
        pos[i] = best[i] < INF_A;
        lab[i] = pos[i] ? slab[bi[i]] : -1;
    }

    // ---- prediction-side (level-major) block-uniform decode ----
    const int j0 = bid << 8;
    int HW, b_f, pix;
    const float *cb, *rb, *ob;
    if (j0 < 131072)      { HW = 16384; b_f = j0 >> 14;            pix = j0 & 16383;           cb = cls0; rb = reg0; ob = ctr0; }
    else if (j0 < 163840) { HW = 4096;  b_f = (j0 - 131072) >> 12; pix = (j0 - 131072) & 4095; cb = cls1; rb = reg1; ob = ctr1; }
    else                  { HW = 1024;  b_f = (j0 - 163840) >> 10; pix = (j0 - 163840) & 1023; cb = cls2; rb = reg2; ob = ctr2; }
    pix += (tid << 2);

    // ---- focal loss: float4 over pixels, exp-based (no abs/select) ----
    const float* cptr = cb + (size_t)(b_f * NCLS) * HW + pix;
    float fsum[4] = {0.f, 0.f, 0.f, 0.f};
    float mx4[4]  = {-INF_A, -INF_A, -INF_A, -INF_A};
    #pragma unroll 4
    for (int c = 0; c < NCLS; c++) {
        const float4 v = *reinterpret_cast<const float4*>(cptr + (size_t)c * HW);
        const float xv[4] = {v.x, v.y, v.z, v.w};
        #pragma unroll
        for (int i = 0; i < 4; i++) {
            const float xx = xv[i];
            mx4[i] = fmaxf(mx4[i], xx);
            const float E  = __expf(xx);
            const float u  = 1.0f + E;
            const float rc = __fdividef(1.0f, u);
            const float pp = E * rc;
            fsum[i] += __log2f(u) * (pp * pp);   // scaled by 0.75*ln2 after loop
        }
    }

    // ---- per-point epilogue: focal scale+correction, GIoU, BCE ----
    const float* rp = rb + (size_t)(b_f * 4) * HW + pix;
    const float* op = ob + (size_t)b_f * HW + pix;
    float4 acc = make_float4(0.f, 0.f, 0.f, 0.f);
    #pragma unroll
    for (int i = 0; i < 4; i++) {
        float f = fsum[i] * LN2_075;
        if (pos[i]) {
            // focal correction for the hit class (reload logit; L1 hit)
            const float xl = cptr[(size_t)lab[i] * HW + i];
            const float E  = __expf(xl);
            const float u  = 1.0f + E;
            const float rc = __fdividef(1.0f, u);
            const float pp = E * rc;
            const float sp = __logf(u);
            f += 0.25f * (sp - xl) * rc * rc - 0.75f * sp * pp * pp;
            acc.x += f;
            acc.w += 1.0f;

            // targets for winning box
            const float4 wb = sbox[bi[i]];
            const float xi = x0 + (float)i * s;
            const float tl = xi - wb.x, tt = y - wb.y, tr = wb.z - xi, tb = wb.w - y;
            const float lrmin = fminf(tl, tr), lrmax = fmaxf(tl, tr);
            const float tbmin = fminf(tt, tb), tbmax = fmaxf(tt, tb);
            const float ratio = __fdividef(lrmin, fmaxf(lrmax, 1e-12f)) *
                                __fdividef(tbmin, fmaxf(tbmax, 1e-12f));
            const float ctr_t = sqrtf(fmaxf(ratio, 0.0f));

            // GIoU
            const float pl  = rp[i];
            const float pt2 = rp[HW + i];
            const float pr  = rp[2 * HW + i];
            const float pb  = rp[3 * HW + i];
            const float t_area = (tl + tr) * (tt + tb);
            const float p_area = (pl + pr) * (pt2 + pb);
            const float w_i = fminf(pl, tl) + fminf(pr, tr);
            const float h_i = fminf(pb, tb) + fminf(pt2, tt);
            const float a_i = w_i * h_i;
            const float a_u = t_area + p_area - a_i;
            const float iou = __fdividef(a_i + 1.0f, a_u + 1.0f);
            const float gw  = fmaxf(pl, tl) + fmaxf(pr, tr);
            const float gh  = fmaxf(pb, tb) + fmaxf(pt2, tt);
            const float ac  = gw * gh;
            acc.y += (1.0f - (iou - __fdividef(ac - a_u, ac))) * ctr_t;

            // centerness BCE
            const float oc = op[i];
            const float e2 = __expf(-fabsf(oc));
            acc.z += fmaxf(oc, 0.0f) + __logf(1.0f + e2) - oc * ctr_t;
        } else {
            // ignore weight: max sigmoid > 0.3  <=>  max logit > ln(3/7)
            if (mx4[i] <= -0.8472978603872037f) acc.x += f;
        }
    }

    // ---- block reduction (2 warps) -> per-block partial ----
    acc = warp_red(acc);
    if ((tid & 31) == 0) sw[tid >> 5] = acc;
    __syncthreads();
    if (tid == 0) {
        float4 a = sw[0], b = sw[1];
        g_part[bid] = make_float4(a.x + b.x, a.y + b.y, a.z + b.z, a.w + b.w);
    }

    // ---- last block finalizes ----
    if (tid == 0) {
        __threadfence();
        unsigned old = atomicAdd(&g_count, 1u);
        s_last = (old == (unsigned)(gridDim.x - 1));
    }
    __syncthreads();
    if (!s_last) return;
    __threadfence();

    float4 a = make_float4(0.f, 0.f, 0.f, 0.f);
    for (int i = tid; i < NBLK; i += 64) {
        const float4* pp = &g_part[i];
        float4 v;
        asm volatile("ld.global.cg.v4.f32 {%0,%1,%2,%3}, [%4];"
                     : "=f"(v.x), "=f"(v.y), "=f"(v.z), "=f"(v.w) : "l"(pp));
        a.x += v.x; a.y += v.y; a.z += v.z; a.w += v.w;
    }
    a = warp_red(a);
    if ((tid & 31) == 0) sw[tid >> 5] = a;
    __syncthreads();
    if (tid == 0) {
        float4 t0 = sw[0], t1 = sw[1];
        float sx = t0.x + t1.x, sy = t0.y + t1.y, sz = t0.z + t1.z, np = t0.w + t1.w;
        float inv = __fdividef(1.0f, fmaxf(np, 1.0f));
        out[0] = sx * inv;
        out[1] = sy * inv;
        out[2] = sz * inv;
        g_count = 0;   // reset for next graph replay
    }
}

extern "C" void kernel_launch(void* const* d_in, const int* in_sizes, int n_in,
                              void* d_out, int out_size) {
    const float *cls0, *cls1, *cls2, *reg0, *reg1, *reg2, *ctr0, *ctr1, *ctr2;
    if (in_sizes[1] == 655360) {   // reference-signature order
        cls0 = (const float*)d_in[0]; cls1 = (const float*)d_in[1]; cls2 = (const float*)d_in[2];
        reg0 = (const float*)d_in[3]; reg1 = (const float*)d_in[4]; reg2 = (const float*)d_in[5];
        ctr0 = (const float*)d_in[6]; ctr1 = (const float*)d_in[7]; ctr2 = (const float*)d_in[8];
    } else {                       // setup_inputs dict order
        cls0 = (const float*)d_in[0]; reg0 = (const float*)d_in[1]; ctr0 = (const float*)d_in[2];
        cls1 = (const float*)d_in[3]; reg1 = (const float*)d_in[4]; ctr1 = (const float*)d_in[5];
        cls2 = (const float*)d_in[6]; reg2 = (const float*)d_in[7]; ctr2 = (const float*)d_in[8];
    }
    const float* boxes  = (const float*)d_in[9];
    const int*   labels = (const int*)d_in[10];

    k_fused<<<NBLK, 64>>>(cls0, cls1, cls2, reg0, reg1, reg2,
                          ctr0, ctr1, ctr2, boxes, labels, (float*)d_out);
}

// round 4
// speedup vs baseline: 1.0017x; 1.0017x over previous
#include <cuda_runtime.h>
#include <math.h>

#define TOTAL_PTS   172032
#define NBLK        672          // blocks; 64 threads x 4 pts = 256 pts/block
#define BLKS_PER_IMG 84          // 21504 / 256
#define INF_A       1.0e8f
#define NCLS        20
#define LN2_075     0.5198603854199589f   // 0.75 * ln(2)

__device__ float4   g_part[NBLK];
__device__ unsigned g_count = 0;

__device__ __forceinline__ float4 warp_red(float4 a) {
    #pragma unroll
    for (int off = 16; off > 0; off >>= 1) {
        a.x += __shfl_down_sync(0xffffffffu, a.x, off);
        a.y += __shfl_down_sync(0xffffffffu, a.y, off);
        a.z += __shfl_down_sync(0xffffffffu, a.z, off);
        a.w += __shfl_down_sync(0xffffffffu, a.w, off);
    }
    return a;
}

// level-specialized argmin over 32 boxes for 4 points sharing y
template<int LV>
__device__ __forceinline__ void assign_boxes(
    const float4* __restrict__ sbox, const float* __restrict__ sarea,
    float x0, float s, float y, float* best, int* bi)
{
    #pragma unroll 8
    for (int m = 0; m < 32; m++) {
        const float4 bb = sbox[m];
        const float  a  = sarea[m];
        const float tt   = y - bb.y;
        const float bo   = bb.w - y;
        const float mntb = fminf(tt, bo);
        const float mxtb = fmaxf(tt, bo);
        #pragma unroll
        for (int i = 0; i < 4; i++) {
            const float xi = x0 + (float)i * s;
            const float l  = xi - bb.x;
            const float r  = bb.z - xi;
            const float mn = fminf(mntb, fminf(l, r));
            const float mx = fmaxf(mxtb, fmaxf(l, r));
            bool ok;
            if (LV == 0)      ok = (mn > 0.0f) & (mx <= 64.0f);
            else if (LV == 1) ok = (mn > 0.0f) & (mx >= 64.0f) & (mx <= 128.0f);
            else              ok = (mn > 0.0f) & (mx >= 128.0f);
            if (ok & (a < best[i])) { best[i] = a; bi[i] = m; }
        }
    }
}

__global__ __launch_bounds__(64) void k_fused(
    const float* __restrict__ cls0, const float* __restrict__ cls1, const float* __restrict__ cls2,
    const float* __restrict__ reg0, const float* __restrict__ reg1, const float* __restrict__ reg2,
    const float* __restrict__ ctr0, const float* __restrict__ ctr1, const float* __restrict__ ctr2,
    const float* __restrict__ boxes, const int* __restrict__ labels,
    float* __restrict__ out)
{
    __shared__ float4 sbox[32];
    __shared__ float  sarea[32];
    __shared__ int    slab[32];
    __shared__ float4 sw[2];
    __shared__ bool   s_last;

    const int tid = threadIdx.x;
    const int bid = blockIdx.x;

    // ---- target-side (batch-major) block-uniform decode ----
    const int b_img = bid / BLKS_PER_IMG;
    const int pblk  = (bid - b_img * BLKS_PER_IMG) << 8;   // point offset in image

    if (tid < 32) {
        float4 bb = reinterpret_cast<const float4*>(boxes)[b_img * 32 + tid];
        sbox[tid]  = bb;
        sarea[tid] = (bb.z - bb.x) * (bb.w - bb.y);
        slab[tid]  = labels[b_img * 32 + tid];
    }

    const int p0 = pblk + (tid << 2);   // first of 4 points (same row/level)
    int lv, pi, Wsh; float s;
    if (pblk < 16384)      { lv = 0; pi = p0;         Wsh = 7; s = 4.0f;  }
    else if (pblk < 20480) { lv = 1; pi = p0 - 16384; Wsh = 6; s = 8.0f;  }
    else                   { lv = 2; pi = p0 - 20480; Wsh = 5; s = 16.0f; }
    const int   hh = pi >> Wsh;
    const int   ww = pi & ((1 << Wsh) - 1);
    const float x0 = ww * s + 0.5f * s;
    const float y  = hh * s + 0.5f * s;

    // ---- prediction-side (level-major) block-uniform decode ----
    const int j0 = bid << 8;
    int HW, b_f, pix;
    const float *cb, *rb, *ob;
    if (j0 < 131072)      { HW = 16384; b_f = j0 >> 14;            pix = j0 & 16383;           cb = cls0; rb = reg0; ob = ctr0; }
    else if (j0 < 163840) { HW = 4096;  b_f = (j0 - 131072) >> 12; pix = (j0 - 131072) & 4095; cb = cls1; rb = reg1; ob = ctr1; }
    else                  { HW = 1024;  b_f = (j0 - 163840) >> 10; pix = (j0 - 163840) & 1023; cb = cls2; rb = reg2; ob = ctr2; }
    pix += (tid << 2);

    // ---- PREFETCH: issue all global loads up front (25 x LDG.128 in flight) ----
    const float* cptr = cb + (size_t)(b_f * NCLS) * HW + pix;
    const float* rp   = rb + (size_t)(b_f * 4) * HW + pix;
    const float* op   = ob + (size_t)b_f * HW + pix;

    float4 v[NCLS];
    #pragma unroll
    for (int c = 0; c < NCLS; c++)
        v[c] = *reinterpret_cast<const float4*>(cptr + (size_t)c * HW);
    float4 rg[4];
    #pragma unroll
    for (int k = 0; k < 4; k++)
        rg[k] = *reinterpret_cast<const float4*>(rp + (size_t)k * HW);
    const float4 oc4 = *reinterpret_cast<const float4*>(op);

    __syncthreads();   // boxes staged

    // ---- box assignment while loads fly: 4 independent argmin chains ----
    float best[4] = {INF_A, INF_A, INF_A, INF_A};
    int   bi[4]   = {0, 0, 0, 0};
    if (lv == 0)      assign_boxes<0>(sbox, sarea, x0, s, y, best, bi);
    else if (lv == 1) assign_boxes<1>(sbox, sarea, x0, s, y, best, bi);
    else              assign_boxes<2>(sbox, sarea, x0, s, y, best, bi);

    bool pos[4]; int lab[4];
    #pragma unroll
    for (int i = 0; i < 4; i++) {
        pos[i] = best[i] < INF_A;
        lab[i] = pos[i] ? slab[bi[i]] : -1;
    }

    // ---- focal loss on prefetched registers ----
    float fsum[4] = {0.f, 0.f, 0.f, 0.f};
    float mx4[4]  = {-INF_A, -INF_A, -INF_A, -INF_A};
    #pragma unroll
    for (int c = 0; c < NCLS; c++) {
        const float xv[4] = {v[c].x, v[c].y, v[c].z, v[c].w};
        #pragma unroll
        for (int i = 0; i < 4; i++) {
            const float xx = xv[i];
            mx4[i] = fmaxf(mx4[i], xx);
            const float E  = __expf(xx);
            const float u  = 1.0f + E;
            const float rc = __fdividef(1.0f, u);
            const float pp = E * rc;
            fsum[i] += __log2f(u) * (pp * pp);   // scaled by 0.75*ln2 after loop
        }
    }

    // ---- per-point epilogue: focal scale+correction, GIoU, BCE ----
    const float occ_a[4] = {oc4.x, oc4.y, oc4.z, oc4.w};
    float4 acc = make_float4(0.f, 0.f, 0.f, 0.f);
    #pragma unroll
    for (int i = 0; i < 4; i++) {
        float f = fsum[i] * LN2_075;
        if (pos[i]) {
            // focal correction for the hit class (reload logit; L1/L2 hit)
            const float xl = cptr[(size_t)lab[i] * HW + i];
            const float E  = __expf(xl);
            const float u  = 1.0f + E;
            const float rc = __fdividef(1.0f, u);
            const float pp = E * rc;
            const float sp = __logf(u);
            f += 0.25f * (sp - xl) * rc * rc - 0.75f * sp * pp * pp;
            acc.x += f;
            acc.w += 1.0f;

            // targets for winning box
            const float4 wb = sbox[bi[i]];
            const float xi = x0 + (float)i * s;
            const float tl = xi - wb.x, tt = y - wb.y, tr = wb.z - xi, tb = wb.w - y;
            const float lrmin = fminf(tl, tr), lrmax = fmaxf(tl, tr);
            const float tbmin = fminf(tt, tb), tbmax = fmaxf(tt, tb);
            const float ratio = __fdividef(lrmin, fmaxf(lrmax, 1e-12f)) *
                                __fdividef(tbmin, fmaxf(tbmax, 1e-12f));
            const float ctr_t = sqrtf(fmaxf(ratio, 0.0f));

            // GIoU from prefetched reg planes
            const float pl  = (i == 0) ? rg[0].x : (i == 1) ? rg[0].y : (i == 2) ? rg[0].z : rg[0].w;
            const float pt2 = (i == 0) ? rg[1].x : (i == 1) ? rg[1].y : (i == 2) ? rg[1].z : rg[1].w;
            const float pr  = (i == 0) ? rg[2].x : (i == 1) ? rg[2].y : (i == 2) ? rg[2].z : rg[2].w;
            const float pb  = (i == 0) ? rg[3].x : (i == 1) ? rg[3].y : (i == 2) ? rg[3].z : rg[3].w;
            const float t_area = (tl + tr) * (tt + tb);
            const float p_area = (pl + pr) * (pt2 + pb);
            const float w_i = fminf(pl, tl) + fminf(pr, tr);
            const float h_i = fminf(pb, tb) + fminf(pt2, tt);
            const float a_i = w_i * h_i;
            const float a_u = t_area + p_area - a_i;
            const float iou = __fdividef(a_i + 1.0f, a_u + 1.0f);
            const float gw  = fmaxf(pl, tl) + fmaxf(pr, tr);
            const float gh  = fmaxf(pb, tb) + fmaxf(pt2, tt);
            const float ac  = gw * gh;
            acc.y += (1.0f - (iou - __fdividef(ac - a_u, ac))) * ctr_t;

            // centerness BCE
            const float oc = occ_a[i];
            const float e2 = __expf(-fabsf(oc));
            acc.z += fmaxf(oc, 0.0f) + __logf(1.0f + e2) - oc * ctr_t;
        } else {
            // ignore weight: max sigmoid > 0.3  <=>  max logit > ln(3/7)
            if (mx4[i] <= -0.8472978603872037f) acc.x += f;
        }
    }

    // ---- block reduction (2 warps) -> per-block partial ----
    acc = warp_red(acc);
    if ((tid & 31) == 0) sw[tid >> 5] = acc;
    __syncthreads();
    if (tid == 0) {
        float4 a = sw[0], b = sw[1];
        g_part[bid] = make_float4(a.x + b.x, a.y + b.y, a.z + b.z, a.w + b.w);
    }

    // ---- last block finalizes ----
    if (tid == 0) {
        __threadfence();
        unsigned old = atomicAdd(&g_count, 1u);
        s_last = (old == (unsigned)(gridDim.x - 1));
    }
    __syncthreads();
    if (!s_last) return;
    __threadfence();

    float4 a = make_float4(0.f, 0.f, 0.f, 0.f);
    for (int i = tid; i < NBLK; i += 64) {
        const float4* pp = &g_part[i];
        float4 vv;
        asm volatile("ld.global.cg.v4.f32 {%0,%1,%2,%3}, [%4];"
                     : "=f"(vv.x), "=f"(vv.y), "=f"(vv.z), "=f"(vv.w) : "l"(pp));
        a.x += vv.x; a.y += vv.y; a.z += vv.z; a.w += vv.w;
    }
    a = warp_red(a);
    if ((tid & 31) == 0) sw[tid >> 5] = a;
    __syncthreads();
    if (tid == 0) {
        float4 t0 = sw[0], t1 = sw[1];
        float sx = t0.x + t1.x, sy = t0.y + t1.y, sz = t0.z + t1.z, np = t0.w + t1.w;
        float inv = __fdividef(1.0f, fmaxf(np, 1.0f));
        out[0] = sx * inv;
        out[1] = sy * inv;
        out[2] = sz * inv;
        g_count = 0;   // reset for next graph replay
    }
}

extern "C" void kernel_launch(void* const* d_in, const int* in_sizes, int n_in,
                              void* d_out, int out_size) {
    const float *cls0, *cls1, *cls2, *reg0, *reg1, *reg2, *ctr0, *ctr1, *ctr2;
    if (in_sizes[1] == 655360) {   // reference-signature order
        cls0 = (const float*)d_in[0]; cls1 = (const float*)d_in[1]; cls2 = (const float*)d_in[2];
        reg0 = (const float*)d_in[3]; reg1 = (const float*)d_in[4]; reg2 = (const float*)d_in[5];
        ctr0 = (const float*)d_in[6]; ctr1 = (const float*)d_in[7]; ctr2 = (const float*)d_in[8];
    } else {                       // setup_inputs dict order
        cls0 = (const float*)d_in[0]; reg0 = (const float*)d_in[1]; ctr0 = (const float*)d_in[2];
        cls1 = (const float*)d_in[3]; reg1 = (const float*)d_in[4]; ctr1 = (const float*)d_in[5];
        cls2 = (const float*)d_in[6]; reg2 = (const float*)d_in[7]; ctr2 = (const float*)d_in[8];
    }
    const float* boxes  = (const float*)d_in[9];
    const int*   labels = (const int*)d_in[10];

    k_fused<<<NBLK, 64>>>(cls0, cls1, cls2, reg0, reg1, reg2,
                          ctr0, ctr1, ctr2, boxes, labels, (float*)d_out);
}

// round 6
// speedup vs baseline: 1.4039x; 1.4015x over previous
#include <cuda_runtime.h>
#include <math.h>

#define TOTAL_PTS   172032
#define NBLK        672          // blocks; 128 threads x 2 pts = 256 pts/block
#define BLKS_PER_IMG 84          // 21504 / 256
#define INF_A       1.0e8f
#define NCLS        20
#define LN2_075     0.5198603854199589f   // 0.75 * ln(2)

__device__ float4   g_part[NBLK];
__device__ unsigned g_count = 0;

__device__ __forceinline__ float4 warp_red(float4 a) {
    #pragma unroll
    for (int off = 16; off > 0; off >>= 1) {
        a.x += __shfl_down_sync(0xffffffffu, a.x, off);
        a.y += __shfl_down_sync(0xffffffffu, a.y, off);
        a.z += __shfl_down_sync(0xffffffffu, a.z, off);
        a.w += __shfl_down_sync(0xffffffffu, a.w, off);
    }
    return a;
}

__global__ __launch_bounds__(128) void k_fused(
    const float* __restrict__ cls0, const float* __restrict__ cls1, const float* __restrict__ cls2,
    const float* __restrict__ reg0, const float* __restrict__ reg1, const float* __restrict__ reg2,
    const float* __restrict__ ctr0, const float* __restrict__ ctr1, const float* __restrict__ ctr2,
    const float* __restrict__ boxes, const int* __restrict__ labels,
    float* __restrict__ out)
{
    __shared__ float4 sbox[32];
    __shared__ float  sarea[32];
    __shared__ int    slab[32];
    __shared__ int    s_n;
    __shared__ float4 sw[4];
    __shared__ bool   s_last;

    const int tid = threadIdx.x;
    const int bid = blockIdx.x;

    // ---- target-side (batch-major) block-uniform decode ----
    const int b_img = bid / BLKS_PER_IMG;
    const int pblk  = (bid - b_img * BLKS_PER_IMG) << 8;   // point offset in image

    int lv, base, Wsh; float s;
    if (pblk < 16384)      { lv = 0; base = 0;     Wsh = 7; s = 4.0f;  }
    else if (pblk < 20480) { lv = 1; base = 16384; Wsh = 6; s = 8.0f;  }
    else                   { lv = 2; base = 20480; Wsh = 5; s = 16.0f; }

    const int p0 = pblk + (tid << 1) - base;     // level-local index of 1st of 2 points
    const int hh = p0 >> Wsh;
    const int ww = p0 & ((1 << Wsh) - 1);
    const float x0 = ww * s + 0.5f * s;
    const float y  = hh * s + 0.5f * s;

    // block y-range (for culling)
    const int lo_blk = pblk - base;
    const float ymin_blk = (float)(lo_blk >> Wsh) * s + 0.5f * s;
    const float ymax_blk = (float)((lo_blk + 255) >> Wsh) * s + 0.5f * s;

    // ---- prediction-side (level-major) block-uniform decode ----
    const int j0 = bid << 8;
    int HW, b_f, pix;
    const float *cb, *rb, *ob;
    if (j0 < 131072)      { HW = 16384; b_f = j0 >> 14;            pix = j0 & 16383;           cb = cls0; rb = reg0; ob = ctr0; }
    else if (j0 < 163840) { HW = 4096;  b_f = (j0 - 131072) >> 12; pix = (j0 - 131072) & 4095; cb = cls1; rb = reg1; ob = ctr1; }
    else                  { HW = 1024;  b_f = (j0 - 163840) >> 10; pix = (j0 - 163840) & 1023; cb = cls2; rb = reg2; ob = ctr2; }
    pix += (tid << 1);

    // ---- PREFETCH: all global loads issued up front (25 x LDG.64) ----
    const float* cptr = cb + (size_t)(b_f * NCLS) * HW + pix;
    const float* rp   = rb + (size_t)(b_f * 4) * HW + pix;
    const float* op   = ob + (size_t)b_f * HW + pix;

    float2 v[NCLS];
    #pragma unroll
    for (int c = 0; c < NCLS; c++)
        v[c] = *reinterpret_cast<const float2*>(cptr + (size_t)c * HW);
    float2 rg[4];
    #pragma unroll
    for (int k = 0; k < 4; k++)
        rg[k] = *reinterpret_cast<const float2*>(rp + (size_t)k * HW);
    const float2 oc2 = *reinterpret_cast<const float2*>(op);

    // ---- box cull + stable compaction (warp 0 only) ----
    if (tid < 32) {
        float4 bb = reinterpret_cast<const float4*>(boxes)[b_img * 32 + tid];
        const float bw = bb.z - bb.x, bh = bb.w - bb.y;
        // y-overlap with block rows (point needs by0 < y < by1)
        bool keep = (bb.y < ymax_blk) & (bb.w > ymin_blk);
        // level feasibility: interior point has mx in [max(w,h)/2, max(w,h))
        if (lv == 0)      keep = keep & (bw <= 128.0f) & (bh <= 128.0f);
        else if (lv == 1) keep = keep & ((bw >= 64.0f)  | (bh >= 64.0f));
        else              keep = keep & ((bw >= 128.0f) | (bh >= 128.0f));
        const unsigned m = __ballot_sync(0xffffffffu, keep);
        if (keep) {
            const int idx = __popc(m & ((1u << tid) - 1u));   // stable -> order preserved
            sbox[idx]  = bb;
            sarea[idx] = bw * bh;
            slab[idx]  = labels[b_img * 32 + tid];
        }
        if (tid == 0) s_n = __popc(m);
    }
    __syncthreads();
    const int nbox = s_n;

    // ---- box assignment over compacted survivors (2 points, shared y) ----
    float best[2] = {INF_A, INF_A};
    int   bi[2]   = {0, 0};
    const float x1 = x0 + s;
    for (int m = 0; m < nbox; m++) {
        const float4 bb = sbox[m];
        const float  a  = sarea[m];
        const float tt   = y - bb.y;
        const float bo   = bb.w - y;
        const float mntb = fminf(tt, bo);
        const float mxtb = fmaxf(tt, bo);
        #pragma unroll
        for (int i = 0; i < 2; i++) {
            const float xi = i ? x1 : x0;
            const float l  = xi - bb.x;
            const float r  = bb.z - xi;
            const float mn = fminf(mntb, fminf(l, r));
            const float mx = fmaxf(mxtb, fmaxf(l, r));
            bool ok;
            if (lv == 0)      ok = (mn > 0.0f) & (mx <= 64.0f);
            else if (lv == 1) ok = (mn > 0.0f) & (mx >= 64.0f) & (mx <= 128.0f);
            else              ok = (mn > 0.0f) & (mx >= 128.0f);
            if (ok & (a < best[i])) { best[i] = a; bi[i] = m; }
        }
    }
    bool pos[2]; int lab[2];
    #pragma unroll
    for (int i = 0; i < 2; i++) {
        pos[i] = best[i] < INF_A;
        lab[i] = pos[i] ? slab[bi[i]] : -1;
    }

    // ---- focal loss on prefetched registers ----
    float fsum[2] = {0.f, 0.f};
    float mx2[2]  = {-INF_A, -INF_A};
    #pragma unroll
    for (int c = 0; c < NCLS; c++) {
        const float xv[2] = {v[c].x, v[c].y};
        #pragma unroll
        for (int i = 0; i < 2; i++) {
            const float xx = xv[i];
            mx2[i] = fmaxf(mx2[i], xx);
            const float E  = __expf(xx);
            const float u  = 1.0f + E;
            const float rc = __fdividef(1.0f, u);
            const float pp = E * rc;
            fsum[i] += __log2f(u) * (pp * pp);   // scaled by 0.75*ln2 after loop
        }
    }

    // ---- per-point epilogue ----
    float4 acc = make_float4(0.f, 0.f, 0.f, 0.f);
    #pragma unroll
    for (int i = 0; i < 2; i++) {
        float f = fsum[i] * LN2_075;
        if (pos[i]) {
            // focal correction for the hit class (reload logit; L1/L2 hit)
            const float xl = cptr[(size_t)lab[i] * HW + i];
            const float E  = __expf(xl);
            const float u  = 1.0f + E;
            const float rc = __fdividef(1.0f, u);
            const float pp = E * rc;
            const float sp = __logf(u);
            f += 0.25f * (sp - xl) * rc * rc - 0.75f * sp * pp * pp;
            acc.x += f;
            acc.w += 1.0f;

            // targets for winning box
            const float4 wb = sbox[bi[i]];
            const float xi = i ? x1 : x0;
            const float tl = xi - wb.x, tt = y - wb.y, tr = wb.z - xi, tb = wb.w - y;
            const float lrmin = fminf(tl, tr), lrmax = fmaxf(tl, tr);
            const float tbmin = fminf(tt, tb), tbmax = fmaxf(tt, tb);
            const float ratio = __fdividef(lrmin, fmaxf(lrmax, 1e-12f)) *
                                __fdividef(tbmin, fmaxf(tbmax, 1e-12f));
            const float ctr_t = sqrtf(fmaxf(ratio, 0.0f));

            // GIoU from prefetched reg planes
            const float pl  = i ? rg[0].y : rg[0].x;
            const float pt2 = i ? rg[1].y : rg[1].x;
            const float pr  = i ? rg[2].y : rg[2].x;
            const float pb  = i ? rg[3].y : rg[3].x;
            const float t_area = (tl + tr) * (tt + tb);
            const float p_area = (pl + pr) * (pt2 + pb);
            const float w_i = fminf(pl, tl) + fminf(pr, tr);
            const float h_i = fminf(pb, tb) + fminf(pt2, tt);
            const float a_i = w_i * h_i;
            const float a_u = t_area + p_area - a_i;
            const float iou = __fdividef(a_i + 1.0f, a_u + 1.0f);
            const float gw  = fmaxf(pl, tl) + fmaxf(pr, tr);
            const float gh  = fmaxf(pb, tb) + fmaxf(pt2, tt);
            const float ac  = gw * gh;
            acc.y += (1.0f - (iou - __fdividef(ac - a_u, ac))) * ctr_t;

            // centerness BCE
            const float oc = i ? oc2.y : oc2.x;
            const float e2 = __expf(-fabsf(oc));
            acc.z += fmaxf(oc, 0.0f) + __logf(1.0f + e2) - oc * ctr_t;
        } else {
            // ignore weight: max sigmoid > 0.3  <=>  max logit > ln(3/7)
            if (mx2[i] <= -0.8472978603872037f) acc.x += f;
        }
    }

    // ---- block reduction (4 warps) -> per-block partial ----
    acc = warp_red(acc);
    if ((tid & 31) == 0) sw[tid >> 5] = acc;
    __syncthreads();
    if (tid == 0) {
        float4 a0 = sw[0], a1 = sw[1], a2 = sw[2], a3 = sw[3];
        g_part[bid] = make_float4(a0.x + a1.x + a2.x + a3.x,
                                  a0.y + a1.y + a2.y + a3.y,
                                  a0.z + a1.z + a2.z + a3.z,
                                  a0.w + a1.w + a2.w + a3.w);
    }

    // ---- last block finalizes ----
    if (tid == 0) {
        __threadfence();
        unsigned old = atomicAdd(&g_count, 1u);
        s_last = (old == (unsigned)(gridDim.x - 1));
    }
    __syncthreads();
    if (!s_last) return;
    __threadfence();

    float4 a = make_float4(0.f, 0.f, 0.f, 0.f);
    for (int i = tid; i < NBLK; i += 128) {
        const float4* pp = &g_part[i];
        float4 vv;
        asm volatile("ld.global.cg.v4.f32 {%0,%1,%2,%3}, [%4];"
                     : "=f"(vv.x), "=f"(vv.y), "=f"(vv.z), "=f"(vv.w) : "l"(pp));
        a.x += vv.x; a.y += vv.y; a.z += vv.z; a.w += vv.w;
    }
    a = warp_red(a);
    if ((tid & 31) == 0) sw[tid >> 5] = a;
    __syncthreads();
    if (tid == 0) {
        float4 t0 = sw[0], t1 = sw[1], t2 = sw[2], t3 = sw[3];
        float sx = t0.x + t1.x + t2.x + t3.x;
        float sy = t0.y + t1.y + t2.y + t3.y;
        float sz = t0.z + t1.z + t2.z + t3.z;
        float np = t0.w + t1.w + t2.w + t3.w;
        float inv = __fdividef(1.0f, fmaxf(np, 1.0f));
        out[0] = sx * inv;
        out[1] = sy * inv;
        out[2] = sz * inv;
        g_count = 0;   // reset for next graph replay
    }
}

extern "C" void kernel_launch(void* const* d_in, const int* in_sizes, int n_in,
                              void* d_out, int out_size) {
    const float *cls0, *cls1, *cls2, *reg0, *reg1, *reg2, *ctr0, *ctr1, *ctr2;
    if (in_sizes[1] == 655360) {   // reference-signature order
        cls0 = (const float*)d_in[0]; cls1 = (const float*)d_in[1]; cls2 = (const float*)d_in[2];
        reg0 = (const float*)d_in[3]; reg1 = (const float*)d_in[4]; reg2 = (const float*)d_in[5];
        ctr0 = (const float*)d_in[6]; ctr1 = (const float*)d_in[7]; ctr2 = (const float*)d_in[8];
    } else {                       // setup_inputs dict order
        cls0 = (const float*)d_in[0]; reg0 = (const float*)d_in[1]; ctr0 = (const float*)d_in[2];
        cls1 = (const float*)d_in[3]; reg1 = (const float*)d_in[4]; ctr1 = (const float*)d_in[5];
        cls2 = (const float*)d_in[6]; reg2 = (const float*)d_in[7]; ctr2 = (const float*)d_in[8];
    }
    const float* boxes  = (const float*)d_in[9];
    const int*   labels = (const int*)d_in[10];

    k_fused<<<NBLK, 128>>>(cls0, cls1, cls2, reg0, reg1, reg2,
                           ctr0, ctr1, ctr2, boxes, labels, (float*)d_out);
}